// round 15
// baseline (speedup 1.0000x reference)
#include <cuda_runtime.h>
#include <cuda_bf16.h>
#include <cstdint>

#define NN 50000
#define NE 800000
#define D  128
#define NG 512
#define CAP 64   // max degree capacity (deg ~ Bin(800K,1/50K): mean 16, max ~38)

// Scratch (no device allocation allowed -> __device__ globals)
__device__ __align__(16) float g_h  [NN * D];
__device__ __align__(16) float g_h2 [NN * D];
__device__ __align__(16) float g_pool[NG * D];
__device__ int g_cnt[NN];          // zero-initialized; re-zeroed by pool_kernel
__device__ int g_adj[NN * CAP];

// ---------------------------------------------------------------------------
// build: zero pool + one-pass bucket adjacency
__global__ void build_kernel(const int* __restrict__ src,
                             const int* __restrict__ dst,
                             int* __restrict__ cnt,
                             int* __restrict__ adj,
                             float* __restrict__ pool) {
    int gtid = blockIdx.x * blockDim.x + threadIdx.x;
    int nthr = gridDim.x * blockDim.x;
    float4 z = make_float4(0.f, 0.f, 0.f, 0.f);
    for (int i = gtid; i < NG * D / 4; i += nthr)
        reinterpret_cast<float4*>(pool)[i] = z;
    for (int e = gtid; e < NE; e += nthr) {
        int d = dst[e];
        int pos = atomicAdd(&cnt[d], 1);
        if (pos < CAP) adj[d * CAP + pos] = src[e];
    }
}

// ---------------------------------------------------------------------------
// pool: contiguous per-warp chunks (batch sorted). Re-zeroes cnt.
#define PCHUNK 32
__global__ void pool_kernel(const float* __restrict__ hin,
                            const int* __restrict__ batch,
                            float* __restrict__ pool,
                            int* __restrict__ cnt) {
    int lane = threadIdx.x & 31;
    int warp = (blockIdx.x * blockDim.x + threadIdx.x) >> 5;
    int nwarp = (gridDim.x * blockDim.x) >> 5;
    int nchunk = (NN + PCHUNK - 1) / PCHUNK;
    for (int c = warp; c < nchunk; c += nwarp) {
        int n0 = c * PCHUNK;
        int n1 = min(n0 + PCHUNK, NN);
        int off = lane * 4;
        int cur = __ldg(&batch[n0]);
        float4 acc = make_float4(0.f, 0.f, 0.f, 0.f);
        for (int n = n0; n < n1; n++) {
            if (lane == 0) cnt[n] = 0;
            int b = __ldg(&batch[n]);
            if (b != cur) {
                float* p = pool + (size_t)cur * D + off;
                asm volatile("red.global.add.v4.f32 [%0], {%1,%2,%3,%4};"
                             :: "l"(p), "f"(acc.x), "f"(acc.y), "f"(acc.z), "f"(acc.w)
                             : "memory");
                acc = make_float4(0.f, 0.f, 0.f, 0.f);
                cur = b;
            }
            float4 v = *reinterpret_cast<const float4*>(hin + (size_t)n * D + off);
            acc.x += v.x; acc.y += v.y; acc.z += v.z; acc.w += v.w;
        }
        float* p = pool + (size_t)cur * D + off;
        asm volatile("red.global.add.v4.f32 [%0], {%1,%2,%3,%4};"
                     :: "l"(p), "f"(acc.x), "f"(acc.y), "f"(acc.z), "f"(acc.w)
                     : "memory");
    }
}

// ===========================================================================
// mma.sync bf16x3 helpers
// ===========================================================================
__device__ __forceinline__ uint32_t bf2(float hi, float lo) {
    uint32_t r;
    asm("cvt.rn.bf16x2.f32 %0, %1, %2;" : "=r"(r) : "f"(hi), "f"(lo));
    return r;
}
__device__ __forceinline__ float bfhi(uint32_t v) {
    return __uint_as_float(v & 0xffff0000u);
}
__device__ __forceinline__ float bflo(uint32_t v) {
    return __uint_as_float(v << 16);
}

#define MMA(c0, c1, c2, c3, a0, a1, a2, a3, b0, b1)                         \
    asm("mma.sync.aligned.m16n8k16.row.col.f32.bf16.bf16.f32 "              \
        "{%0,%1,%2,%3}, {%4,%5,%6,%7}, {%8,%9}, {%0,%1,%2,%3};"             \
        : "+f"(c0), "+f"(c1), "+f"(c2), "+f"(c3)                            \
        : "r"(a0), "r"(a1), "r"(a2), "r"(a3), "r"(b0), "r"(b1))

#define BAR_ARRIVE(id) asm volatile("bar.arrive %0, 256;" :: "r"(id))
#define BAR_SYNC(id)   asm volatile("bar.sync %0, 256;" :: "r"(id) : "memory")

// Pack one weight matrix into INTERLEAVED hi/lo mma-B frags:
// WP[(ks*16+nt)*32+lane] = {bh0, bh1, bl0, bl1}
__device__ __forceinline__ void pack_w(const float* __restrict__ W,
                                       uint4* WP, int tid, int nthr) {
    for (int idx = tid; idx < 8 * 16 * 32; idx += nthr) {
        int l = idx & 31;
        int nt = (idx >> 5) & 15;
        int ks = idx >> 9;
        int col = nt * 8 + (l >> 2);
        int k0 = ks * 16 + (l & 3) * 2;
        float w00 = __ldg(&W[(size_t)k0 * 128 + col]);
        float w01 = __ldg(&W[(size_t)(k0 + 1) * 128 + col]);
        float w10 = __ldg(&W[(size_t)(k0 + 8) * 128 + col]);
        float w11 = __ldg(&W[(size_t)(k0 + 9) * 128 + col]);
        uint32_t h0 = bf2(w01, w00);
        uint32_t h1 = bf2(w11, w10);
        uint4 p;
        p.x = h0;
        p.y = h1;
        p.z = bf2(w01 - bfhi(h0), w00 - bflo(h0));
        p.w = bf2(w11 - bfhi(h1), w10 - bflo(h1));
        WP[idx] = p;
    }
}

// ===========================================================================
// Fused GIN layer: out = relu(relu((x+Agg x)@Wa+ba)@Wb+bb).
// Warp-specialized: warps 0-3 gather 64-row tiles into double-buffered
// bf16 hi/lo A-frag smem; warps 4-7 run both MMA passes + epilogue.
// NOTE: hin and out must NOT alias (cross-CTA gather/store race otherwise).
#define TILE_M  64
#define F_BIAS1 0
#define F_BIAS2 512
#define F_WA    1024
#define F_WB    66560
#define F_AB0   132096
#define ABUF_SZ 33792           // AH (16896) + AL (16896)
#define F_SMEM  (132096 + 2 * ABUF_SZ)   // 199680

__global__ __launch_bounds__(256, 1)
void layer_kernel(const float* __restrict__ hin,
                  const int* __restrict__ cnt,
                  const int* __restrict__ adj,
                  const float* __restrict__ Wa, const float* __restrict__ ba,
                  const float* __restrict__ Wb, const float* __restrict__ bb,
                  float* __restrict__ out, int M) {
    extern __shared__ char smc[];
    float* bs1 = reinterpret_cast<float*>(smc + F_BIAS1);
    float* bs2 = reinterpret_cast<float*>(smc + F_BIAS2);
    uint4* WPa = reinterpret_cast<uint4*>(smc + F_WA);
    uint4* WPb = reinterpret_cast<uint4*>(smc + F_WB);

    int tid = threadIdx.x;
    int wid = tid >> 5;
    int lane = tid & 31;
    int lg = lane >> 2;
    int lt = lane & 3;

    pack_w(Wa, WPa, tid, 256);
    pack_w(Wb, WPb, tid, 256);
    if (tid < 128) { bs1[tid] = ba[tid]; bs2[tid] = bb[tid]; }
    __syncthreads();

    // Per-lane A-frag store indices (producer): row r in tile, k0 = lane*4
    int p_ks = lane >> 2;
    int p_kk = (lane & 3) * 4;
    int p_t0 = (p_kk & 7) >> 1;
    int p_rhi = (p_kk >= 8) ? 2 : 0;

    int ntiles = (M + TILE_M - 1) / TILE_M;
    int it = 0;
    for (int tile = blockIdx.x; tile < ntiles; tile += gridDim.x, it++) {
        int b = it & 1;
        int row0 = tile * TILE_M;
        uint32_t* AH = reinterpret_cast<uint32_t*>(smc + F_AB0 + b * ABUF_SZ);
        uint32_t* AL = AH + 4224;

        if (wid < 4) {
            // ================= PRODUCER =================
            if (it >= 2) BAR_SYNC(3 + b);   // wait buffer empty
#pragma unroll 1
            for (int i = 0; i < 16; i++) {
                int r = wid * 16 + i;
                int gr = row0 + r;
                float4 a0 = make_float4(0.f, 0.f, 0.f, 0.f);
                if (gr < M) {
                    int off = lane * 4;
                    int end = __ldg(&cnt[gr]);
                    const int* lst = adj + (size_t)gr * CAP;
                    a0 = *reinterpret_cast<const float4*>(hin + (size_t)gr * D + off);
                    float4 a1 = make_float4(0.f, 0.f, 0.f, 0.f);
                    float4 a2 = make_float4(0.f, 0.f, 0.f, 0.f);
                    float4 a3 = make_float4(0.f, 0.f, 0.f, 0.f);
                    int k = 0;
                    for (; k + 8 <= end; k += 8) {
                        int s0 = __ldg(&lst[k]);
                        int s1 = __ldg(&lst[k + 1]);
                        int s2 = __ldg(&lst[k + 2]);
                        int s3 = __ldg(&lst[k + 3]);
                        int s4 = __ldg(&lst[k + 4]);
                        int s5 = __ldg(&lst[k + 5]);
                        int s6 = __ldg(&lst[k + 6]);
                        int s7 = __ldg(&lst[k + 7]);
                        float4 v0 = *reinterpret_cast<const float4*>(hin + (size_t)s0 * D + off);
                        float4 v1 = *reinterpret_cast<const float4*>(hin + (size_t)s1 * D + off);
                        float4 v2 = *reinterpret_cast<const float4*>(hin + (size_t)s2 * D + off);
                        float4 v3 = *reinterpret_cast<const float4*>(hin + (size_t)s3 * D + off);
                        float4 v4 = *reinterpret_cast<const float4*>(hin + (size_t)s4 * D + off);
                        float4 v5 = *reinterpret_cast<const float4*>(hin + (size_t)s5 * D + off);
                        float4 v6 = *reinterpret_cast<const float4*>(hin + (size_t)s6 * D + off);
                        float4 v7 = *reinterpret_cast<const float4*>(hin + (size_t)s7 * D + off);
                        a0.x += v0.x + v4.x; a0.y += v0.y + v4.y;
                        a0.z += v0.z + v4.z; a0.w += v0.w + v4.w;
                        a1.x += v1.x + v5.x; a1.y += v1.y + v5.y;
                        a1.z += v1.z + v5.z; a1.w += v1.w + v5.w;
                        a2.x += v2.x + v6.x; a2.y += v2.y + v6.y;
                        a2.z += v2.z + v6.z; a2.w += v2.w + v6.w;
                        a3.x += v3.x + v7.x; a3.y += v3.y + v7.y;
                        a3.z += v3.z + v7.z; a3.w += v3.w + v7.w;
                    }
                    if (k + 4 <= end) {
                        int s0 = __ldg(&lst[k]);
                        int s1 = __ldg(&lst[k + 1]);
                        int s2 = __ldg(&lst[k + 2]);
                        int s3 = __ldg(&lst[k + 3]);
                        float4 v0 = *reinterpret_cast<const float4*>(hin + (size_t)s0 * D + off);
                        float4 v1 = *reinterpret_cast<const float4*>(hin + (size_t)s1 * D + off);
                        float4 v2 = *reinterpret_cast<const float4*>(hin + (size_t)s2 * D + off);
                        float4 v3 = *reinterpret_cast<const float4*>(hin + (size_t)s3 * D + off);
                        a0.x += v0.x; a0.y += v0.y; a0.z += v0.z; a0.w += v0.w;
                        a1.x += v1.x; a1.y += v1.y; a1.z += v1.z; a1.w += v1.w;
                        a2.x += v2.x; a2.y += v2.y; a2.z += v2.z; a2.w += v2.w;
                        a3.x += v3.x; a3.y += v3.y; a3.z += v3.z; a3.w += v3.w;
                        k += 4;
                    }
                    for (; k < end; k++) {
                        int s = __ldg(&lst[k]);
                        float4 v = *reinterpret_cast<const float4*>(hin + (size_t)s * D + off);
                        a0.x += v.x; a0.y += v.y; a0.z += v.z; a0.w += v.w;
                    }
                    a0.x += a1.x + a2.x + a3.x;
                    a0.y += a1.y + a2.y + a3.y;
                    a0.z += a1.z + a2.z + a3.z;
                    a0.w += a1.w + a2.w + a3.w;
                }
                // split + store in mma A-frag order (k0 = lane*4)
                uint32_t h0 = bf2(a0.y, a0.x);
                uint32_t h1 = bf2(a0.w, a0.z);
                uint32_t l0 = bf2(a0.y - bfhi(h0), a0.x - bflo(h0));
                uint32_t l1 = bf2(a0.w - bfhi(h1), a0.z - bflo(h1));
                int mt = r >> 4;
                int g = r & 15;
                int reg = p_rhi + ((g >= 8) ? 1 : 0);
                int base16 = (mt * 8 + p_ks) * 33 + (g & 7) * 4 + p_t0;
                AH[base16 * 4 + reg]       = h0;
                AH[(base16 + 1) * 4 + reg] = h1;
                AL[base16 * 4 + reg]       = l0;
                AL[(base16 + 1) * 4 + reg] = l1;
            }
            asm volatile("membar.cta;" ::: "memory");
            BAR_ARRIVE(1 + b);               // buffer full
        } else {
            // ================= CONSUMER =================
            int cw = wid - 4;
            BAR_SYNC(1 + b);                 // wait buffer full

            float acc[16][4];
#pragma unroll
            for (int nt = 0; nt < 16; nt++)
#pragma unroll
                for (int j = 0; j < 4; j++) acc[nt][j] = 0.f;

#pragma unroll
            for (int ks = 0; ks < 8; ks++) {
                int ab = ((cw * 8 + ks) * 33 + lane) * 4;
                uint4 ah = *reinterpret_cast<uint4*>(&AH[ab]);
                uint4 al = *reinterpret_cast<uint4*>(&AL[ab]);
#pragma unroll
                for (int nt = 0; nt < 16; nt++) {
                    uint4 w = WPa[(ks * 16 + nt) * 32 + lane];
                    MMA(acc[nt][0], acc[nt][1], acc[nt][2], acc[nt][3],
                        ah.x, ah.y, ah.z, ah.w, w.x, w.y);
                    MMA(acc[nt][0], acc[nt][1], acc[nt][2], acc[nt][3],
                        al.x, al.y, al.z, al.w, w.x, w.y);
                    MMA(acc[nt][0], acc[nt][1], acc[nt][2], acc[nt][3],
                        ah.x, ah.y, ah.z, ah.w, w.z, w.w);
                }
            }
            BAR_ARRIVE(3 + b);               // A smem consumed -> buffer empty

            // register epilogue 1 -> A-frags for pass 2
            uint4 fah[8], fal[8];
#pragma unroll
            for (int ks = 0; ks < 8; ks++) {
                int nt0 = 2 * ks, nt1 = 2 * ks + 1;
                int c0 = nt0 * 8 + lt * 2;
                int c1 = nt1 * 8 + lt * 2;
                float t00 = fmaxf(acc[nt0][0] + bs1[c0],     0.f);
                float t01 = fmaxf(acc[nt0][1] + bs1[c0 + 1], 0.f);
                float t10 = fmaxf(acc[nt0][2] + bs1[c0],     0.f);
                float t11 = fmaxf(acc[nt0][3] + bs1[c0 + 1], 0.f);
                float u00 = fmaxf(acc[nt1][0] + bs1[c1],     0.f);
                float u01 = fmaxf(acc[nt1][1] + bs1[c1 + 1], 0.f);
                float u10 = fmaxf(acc[nt1][2] + bs1[c1],     0.f);
                float u11 = fmaxf(acc[nt1][3] + bs1[c1 + 1], 0.f);
                uint32_t h;
                h = bf2(t01, t00); fah[ks].x = h;
                fal[ks].x = bf2(t01 - bfhi(h), t00 - bflo(h));
                h = bf2(t11, t10); fah[ks].y = h;
                fal[ks].y = bf2(t11 - bfhi(h), t10 - bflo(h));
                h = bf2(u01, u00); fah[ks].z = h;
                fal[ks].z = bf2(u01 - bfhi(h), u00 - bflo(h));
                h = bf2(u11, u10); fah[ks].w = h;
                fal[ks].w = bf2(u11 - bfhi(h), u10 - bflo(h));
            }

            // pass 2
#pragma unroll
            for (int nt = 0; nt < 16; nt++)
#pragma unroll
                for (int j = 0; j < 4; j++) acc[nt][j] = 0.f;

#pragma unroll
            for (int ks = 0; ks < 8; ks++) {
                uint4 ah = fah[ks];
                uint4 al = fal[ks];
#pragma unroll
                for (int nt = 0; nt < 16; nt++) {
                    uint4 w = WPb[(ks * 16 + nt) * 32 + lane];
                    MMA(acc[nt][0], acc[nt][1], acc[nt][2], acc[nt][3],
                        ah.x, ah.y, ah.z, ah.w, w.x, w.y);
                    MMA(acc[nt][0], acc[nt][1], acc[nt][2], acc[nt][3],
                        al.x, al.y, al.z, al.w, w.x, w.y);
                    MMA(acc[nt][0], acc[nt][1], acc[nt][2], acc[nt][3],
                        ah.x, ah.y, ah.z, ah.w, w.z, w.w);
                }
            }

            // epilogue 2: bias + relu + store
            int r0 = row0 + cw * 16 + lg;
            int r1 = r0 + 8;
#pragma unroll
            for (int nt = 0; nt < 16; nt++) {
                int c = nt * 8 + lt * 2;
                float b0v = bs2[c], b1v = bs2[c + 1];
                if (r0 < M) {
                    float2 o;
                    o.x = fmaxf(acc[nt][0] + b0v, 0.f);
                    o.y = fmaxf(acc[nt][1] + b1v, 0.f);
                    *reinterpret_cast<float2*>(out + (size_t)r0 * D + c) = o;
                }
                if (r1 < M) {
                    float2 o;
                    o.x = fmaxf(acc[nt][2] + b0v, 0.f);
                    o.y = fmaxf(acc[nt][3] + b1v, 0.f);
                    *reinterpret_cast<float2*>(out + (size_t)r1 * D + c) = o;
                }
            }
        }
    }
}

// ===========================================================================
// Single GEMM (for FC head): out = relu(A@W + bias)
#define SM_BIAS 0
#define SM_W    512
#define SM_AH   66048
#define SM_AL   99840
#define TG_SMEM 133632

__global__ __launch_bounds__(256, 1)
void tgemm_kernel(const float* __restrict__ A, const float* __restrict__ W,
                  const float* __restrict__ bias, float* __restrict__ out,
                  int M) {
    extern __shared__ char smc[];
    float* bsm = reinterpret_cast<float*>(smc + SM_BIAS);
    uint4* WP  = reinterpret_cast<uint4*>(smc + SM_W);
    uint32_t* AH = reinterpret_cast<uint32_t*>(smc + SM_AH);
    uint32_t* AL = reinterpret_cast<uint32_t*>(smc + SM_AL);

    int tid = threadIdx.x;
    int wid = tid >> 5;
    int lane = tid & 31;
    int lg = lane >> 2;
    int lt = lane & 3;

    pack_w(W, WP, tid, 256);
    if (tid < 128) bsm[tid] = bias[tid];

    int ntiles = (M + 127) >> 7;
    for (int tile = blockIdx.x; tile < ntiles; tile += gridDim.x) {
        int row0 = tile << 7;
        __syncthreads();
#pragma unroll
        for (int j = 0; j < 16; j++) {
            int i4 = tid + 256 * j;
            int r = i4 >> 5;
            int q = i4 & 31;
            int k0 = q * 4;
            int gr = row0 + r;
            float4 v = make_float4(0.f, 0.f, 0.f, 0.f);
            if (gr < M)
                v = reinterpret_cast<const float4*>(A + (size_t)gr * D)[q];
            uint32_t h0 = bf2(v.y, v.x);
            uint32_t h1 = bf2(v.w, v.z);
            uint32_t l0 = bf2(v.y - bfhi(h0), v.x - bflo(h0));
            uint32_t l1 = bf2(v.w - bfhi(h1), v.z - bflo(h1));
            int mt = r >> 4;
            int g = r & 15;
            int ks = k0 >> 4;
            int kk = k0 & 15;
            int t0 = (kk & 7) >> 1;
            int reg = ((kk >= 8) ? 2 : 0) + ((g >= 8) ? 1 : 0);
            int base16 = (mt * 8 + ks) * 33 + (g & 7) * 4 + t0;
            AH[base16 * 4 + reg]       = h0;
            AH[(base16 + 1) * 4 + reg] = h1;
            AL[base16 * 4 + reg]       = l0;
            AL[(base16 + 1) * 4 + reg] = l1;
        }
        __syncthreads();

        float acc[16][4];
#pragma unroll
        for (int nt = 0; nt < 16; nt++)
#pragma unroll
            for (int j = 0; j < 4; j++) acc[nt][j] = 0.f;

#pragma unroll
        for (int ks = 0; ks < 8; ks++) {
            int ab = ((wid * 8 + ks) * 33 + lane) * 4;
            uint4 ah = *reinterpret_cast<uint4*>(&AH[ab]);
            uint4 al = *reinterpret_cast<uint4*>(&AL[ab]);
#pragma unroll
            for (int nt = 0; nt < 16; nt++) {
                uint4 w = WP[(ks * 16 + nt) * 32 + lane];
                MMA(acc[nt][0], acc[nt][1], acc[nt][2], acc[nt][3],
                    ah.x, ah.y, ah.z, ah.w, w.x, w.y);
                MMA(acc[nt][0], acc[nt][1], acc[nt][2], acc[nt][3],
                    al.x, al.y, al.z, al.w, w.x, w.y);
                MMA(acc[nt][0], acc[nt][1], acc[nt][2], acc[nt][3],
                    ah.x, ah.y, ah.z, ah.w, w.z, w.w);
            }
        }

        int r0 = row0 + wid * 16 + lg;
        int r1 = r0 + 8;
#pragma unroll
        for (int nt = 0; nt < 16; nt++) {
            int c = nt * 8 + lt * 2;
            float b0v = bsm[c], b1v = bsm[c + 1];
            if (r0 < M) {
                float2 o;
                o.x = fmaxf(acc[nt][0] + b0v, 0.f);
                o.y = fmaxf(acc[nt][1] + b1v, 0.f);
                *reinterpret_cast<float2*>(out + (size_t)r0 * D + c) = o;
            }
            if (r1 < M) {
                float2 o;
                o.x = fmaxf(acc[nt][2] + b0v, 0.f);
                o.y = fmaxf(acc[nt][3] + b1v, 0.f);
                *reinterpret_cast<float2*>(out + (size_t)r1 * D + c) = o;
            }
        }
    }
}

// ---------------------------------------------------------------------------
extern "C" void kernel_launch(void* const* d_in, const int* in_sizes, int n_in,
                              void* d_out, int out_size) {
    const float* x = (const float*)d_in[0];
    const int* ei = (const int*)d_in[1];       // int32 (JAX x64 disabled)
    const int* batch = (const int*)d_in[2];    // int32
    const float* W1a = (const float*)d_in[3];
    const float* b1a = (const float*)d_in[4];
    const float* W1b = (const float*)d_in[5];
    const float* b1b = (const float*)d_in[6];
    const float* W2a = (const float*)d_in[7];
    const float* b2a = (const float*)d_in[8];
    const float* W2b = (const float*)d_in[9];
    const float* b2b = (const float*)d_in[10];
    const float* Wfc = (const float*)d_in[11];
    const float* bfc = (const float*)d_in[12];
    float* out = (float*)d_out;

    const int* src = ei;
    const int* dst = ei + NE;

    float *h, *h2, *pool;
    int *cnt, *adj;
    cudaGetSymbolAddress((void**)&h, g_h);
    cudaGetSymbolAddress((void**)&h2, g_h2);
    cudaGetSymbolAddress((void**)&pool, g_pool);
    cudaGetSymbolAddress((void**)&cnt, g_cnt);
    cudaGetSymbolAddress((void**)&adj, g_adj);

    cudaFuncSetAttribute(layer_kernel,
                         cudaFuncAttributeMaxDynamicSharedMemorySize, F_SMEM);
    cudaFuncSetAttribute(tgemm_kernel,
                         cudaFuncAttributeMaxDynamicSharedMemorySize, TG_SMEM);

    // Adjacency build (cnt zeroed by pool_kernel each call) + pool zeroing
    build_kernel<<<1024, 256>>>(src, dst, cnt, adj, pool);

    // Fused layers (gather + MLP, warp-specialized); ping-pong h -> h2
    layer_kernel<<<148, 256, F_SMEM>>>(x, cnt, adj, W1a, b1a, W1b, b1b, h, NN);
    layer_kernel<<<148, 256, F_SMEM>>>(h, cnt, adj, W2a, b2a, W2b, b2b, h2, NN);

    // Global add pool (also re-zeroes cnt) + FC head
    pool_kernel<<<196, 256>>>(h2, batch, pool, cnt);
    tgemm_kernel<<<4, 256, TG_SMEM>>>(pool, Wfc, bfc, out, NG);
}

// round 16
// speedup vs baseline: 2.0590x; 2.0590x over previous
#include <cuda_runtime.h>
#include <cuda_bf16.h>
#include <cstdint>

#define NN 50000
#define NE 800000
#define D  128
#define NG 512
#define CAP 64   // max degree capacity (deg ~ Bin(800K,1/50K): mean 16, max ~38)

// Scratch (no device allocation allowed -> __device__ globals)
__device__ __align__(16) float g_agg[NN * D];
__device__ __align__(16) float g_h  [NN * D];
__device__ __align__(16) float g_pool[NG * D];
__device__ int g_cnt[NN];          // zero-initialized; re-zeroed by pool_kernel
__device__ int g_adj[NN * CAP];

// ---------------------------------------------------------------------------
// build: zero pool + one-pass bucket adjacency
__global__ void build_kernel(const int* __restrict__ src,
                             const int* __restrict__ dst,
                             int* __restrict__ cnt,
                             int* __restrict__ adj,
                             float* __restrict__ pool) {
    int gtid = blockIdx.x * blockDim.x + threadIdx.x;
    int nthr = gridDim.x * blockDim.x;
    float4 z = make_float4(0.f, 0.f, 0.f, 0.f);
    for (int i = gtid; i < NG * D / 4; i += nthr)
        reinterpret_cast<float4*>(pool)[i] = z;
    for (int e = gtid; e < NE; e += nthr) {
        int d = dst[e];
        int pos = atomicAdd(&cnt[d], 1);
        if (pos < CAP) adj[d * CAP + pos] = src[e];
    }
}

// ---------------------------------------------------------------------------
// aggregate: warp per node; 8-deep gather pipeline. At LTS throughput roof.
__global__ void agg_kernel(const float* __restrict__ hin,
                           const int* __restrict__ cnt,
                           const int* __restrict__ adj,
                           float* __restrict__ out) {
    int lane = threadIdx.x & 31;
    int warp = (blockIdx.x * blockDim.x + threadIdx.x) >> 5;
    int nwarp = (gridDim.x * blockDim.x) >> 5;
    for (int n = warp; n < NN; n += nwarp) {
        int end = __ldg(&cnt[n]);
        const int* lst = adj + n * CAP;
        int off = lane * 4;
        float4 a0 = *reinterpret_cast<const float4*>(hin + (size_t)n * D + off);
        float4 a1 = make_float4(0.f, 0.f, 0.f, 0.f);
        float4 a2 = make_float4(0.f, 0.f, 0.f, 0.f);
        float4 a3 = make_float4(0.f, 0.f, 0.f, 0.f);
        int k = 0;
        for (; k + 8 <= end; k += 8) {
            int s0 = __ldg(&lst[k]);
            int s1 = __ldg(&lst[k + 1]);
            int s2 = __ldg(&lst[k + 2]);
            int s3 = __ldg(&lst[k + 3]);
            int s4 = __ldg(&lst[k + 4]);
            int s5 = __ldg(&lst[k + 5]);
            int s6 = __ldg(&lst[k + 6]);
            int s7 = __ldg(&lst[k + 7]);
            float4 v0 = *reinterpret_cast<const float4*>(hin + (size_t)s0 * D + off);
            float4 v1 = *reinterpret_cast<const float4*>(hin + (size_t)s1 * D + off);
            float4 v2 = *reinterpret_cast<const float4*>(hin + (size_t)s2 * D + off);
            float4 v3 = *reinterpret_cast<const float4*>(hin + (size_t)s3 * D + off);
            float4 v4 = *reinterpret_cast<const float4*>(hin + (size_t)s4 * D + off);
            float4 v5 = *reinterpret_cast<const float4*>(hin + (size_t)s5 * D + off);
            float4 v6 = *reinterpret_cast<const float4*>(hin + (size_t)s6 * D + off);
            float4 v7 = *reinterpret_cast<const float4*>(hin + (size_t)s7 * D + off);
            a0.x += v0.x + v4.x; a0.y += v0.y + v4.y;
            a0.z += v0.z + v4.z; a0.w += v0.w + v4.w;
            a1.x += v1.x + v5.x; a1.y += v1.y + v5.y;
            a1.z += v1.z + v5.z; a1.w += v1.w + v5.w;
            a2.x += v2.x + v6.x; a2.y += v2.y + v6.y;
            a2.z += v2.z + v6.z; a2.w += v2.w + v6.w;
            a3.x += v3.x + v7.x; a3.y += v3.y + v7.y;
            a3.z += v3.z + v7.z; a3.w += v3.w + v7.w;
        }
        if (k + 4 <= end) {
            int s0 = __ldg(&lst[k]);
            int s1 = __ldg(&lst[k + 1]);
            int s2 = __ldg(&lst[k + 2]);
            int s3 = __ldg(&lst[k + 3]);
            float4 v0 = *reinterpret_cast<const float4*>(hin + (size_t)s0 * D + off);
            float4 v1 = *reinterpret_cast<const float4*>(hin + (size_t)s1 * D + off);
            float4 v2 = *reinterpret_cast<const float4*>(hin + (size_t)s2 * D + off);
            float4 v3 = *reinterpret_cast<const float4*>(hin + (size_t)s3 * D + off);
            a0.x += v0.x; a0.y += v0.y; a0.z += v0.z; a0.w += v0.w;
            a1.x += v1.x; a1.y += v1.y; a1.z += v1.z; a1.w += v1.w;
            a2.x += v2.x; a2.y += v2.y; a2.z += v2.z; a2.w += v2.w;
            a3.x += v3.x; a3.y += v3.y; a3.z += v3.z; a3.w += v3.w;
            k += 4;
        }
        for (; k < end; k++) {
            int s = __ldg(&lst[k]);
            float4 v = *reinterpret_cast<const float4*>(hin + (size_t)s * D + off);
            a0.x += v.x; a0.y += v.y; a0.z += v.z; a0.w += v.w;
        }
        a0.x += a1.x + a2.x + a3.x;
        a0.y += a1.y + a2.y + a3.y;
        a0.z += a1.z + a2.z + a3.z;
        a0.w += a1.w + a2.w + a3.w;
        *reinterpret_cast<float4*>(out + (size_t)n * D + off) = a0;
    }
}

// ---------------------------------------------------------------------------
// pool: small per-warp chunks (batch sorted -> register runs). Re-zeroes cnt.
// PCHUNK=8 + 784 blocks: 4x warp parallelism vs PCHUNK=32/196 (latency-bound).
#define PCHUNK 8
__global__ void pool_kernel(const float* __restrict__ hin,
                            const int* __restrict__ batch,
                            float* __restrict__ pool,
                            int* __restrict__ cnt) {
    int lane = threadIdx.x & 31;
    int warp = (blockIdx.x * blockDim.x + threadIdx.x) >> 5;
    int nwarp = (gridDim.x * blockDim.x) >> 5;
    int nchunk = (NN + PCHUNK - 1) / PCHUNK;
    for (int c = warp; c < nchunk; c += nwarp) {
        int n0 = c * PCHUNK;
        int n1 = min(n0 + PCHUNK, NN);
        int off = lane * 4;
        int cur = __ldg(&batch[n0]);
        float4 acc = make_float4(0.f, 0.f, 0.f, 0.f);
        for (int n = n0; n < n1; n++) {
            if (lane == 0) cnt[n] = 0;
            int b = __ldg(&batch[n]);
            if (b != cur) {
                float* p = pool + (size_t)cur * D + off;
                asm volatile("red.global.add.v4.f32 [%0], {%1,%2,%3,%4};"
                             :: "l"(p), "f"(acc.x), "f"(acc.y), "f"(acc.z), "f"(acc.w)
                             : "memory");
                acc = make_float4(0.f, 0.f, 0.f, 0.f);
                cur = b;
            }
            float4 v = *reinterpret_cast<const float4*>(hin + (size_t)n * D + off);
            acc.x += v.x; acc.y += v.y; acc.z += v.z; acc.w += v.w;
        }
        float* p = pool + (size_t)cur * D + off;
        asm volatile("red.global.add.v4.f32 [%0], {%1,%2,%3,%4};"
                     :: "l"(p), "f"(acc.x), "f"(acc.y), "f"(acc.z), "f"(acc.w)
                     : "memory");
    }
}

// ===========================================================================
// mma.sync bf16x3 helpers
// ===========================================================================
__device__ __forceinline__ uint32_t bf2(float hi, float lo) {
    uint32_t r;
    asm("cvt.rn.bf16x2.f32 %0, %1, %2;" : "=r"(r) : "f"(hi), "f"(lo));
    return r;
}
__device__ __forceinline__ float bfhi(uint32_t v) {
    return __uint_as_float(v & 0xffff0000u);
}
__device__ __forceinline__ float bflo(uint32_t v) {
    return __uint_as_float(v << 16);
}

#define MMA(c0, c1, c2, c3, a0, a1, a2, a3, b0, b1)                         \
    asm("mma.sync.aligned.m16n8k16.row.col.f32.bf16.bf16.f32 "              \
        "{%0,%1,%2,%3}, {%4,%5,%6,%7}, {%8,%9}, {%0,%1,%2,%3};"             \
        : "+f"(c0), "+f"(c1), "+f"(c2), "+f"(c3)                            \
        : "r"(a0), "r"(a1), "r"(a2), "r"(a3), "r"(b0), "r"(b1))

// Pack one weight matrix into INTERLEAVED hi/lo mma-B frags:
// WP[(ks*16+nt)*32+lane] = {bh0, bh1, bl0, bl1}  -> one LDS.128 in inner loop.
__device__ __forceinline__ void pack_w(const float* __restrict__ W,
                                       uint4* WP, int tid) {
    for (int idx = tid; idx < 8 * 16 * 32; idx += 256) {
        int l = idx & 31;
        int nt = (idx >> 5) & 15;
        int ks = idx >> 9;
        int col = nt * 8 + (l >> 2);
        int k0 = ks * 16 + (l & 3) * 2;
        float w00 = __ldg(&W[(size_t)k0 * 128 + col]);
        float w01 = __ldg(&W[(size_t)(k0 + 1) * 128 + col]);
        float w10 = __ldg(&W[(size_t)(k0 + 8) * 128 + col]);
        float w11 = __ldg(&W[(size_t)(k0 + 9) * 128 + col]);
        uint32_t h0 = bf2(w01, w00);
        uint32_t h1 = bf2(w11, w10);
        uint4 p;
        p.x = h0;
        p.y = h1;
        p.z = bf2(w01 - bfhi(h0), w00 - bflo(h0));
        p.w = bf2(w11 - bfhi(h1), w10 - bflo(h1));
        WP[idx] = p;
    }
}

// ===========================================================================
// Fused MLP kernel: out = relu(relu(A@Wa+ba)@Wb+bb). Intermediate t stays in
// registers (mma C-layout == next mma A-layout).
// SMEM: bias 1KB | WPa 64KB | WPb 64KB | AH 33KB | AL 33KB -> 199680 B
#define F_BIAS1 0
#define F_BIAS2 512
#define F_WA    1024
#define F_WB    66560
#define F_AH    132096
#define F_AL    165888
#define F_SMEM  199680

__global__ __launch_bounds__(256, 1)
void mlp_kernel(const float* __restrict__ A,
                const float* __restrict__ Wa, const float* __restrict__ ba,
                const float* __restrict__ Wb, const float* __restrict__ bb,
                float* __restrict__ out, int M) {
    extern __shared__ char smc[];
    float* bs1 = reinterpret_cast<float*>(smc + F_BIAS1);
    float* bs2 = reinterpret_cast<float*>(smc + F_BIAS2);
    uint4* WPa = reinterpret_cast<uint4*>(smc + F_WA);
    uint4* WPb = reinterpret_cast<uint4*>(smc + F_WB);
    uint32_t* AH = reinterpret_cast<uint32_t*>(smc + F_AH);
    uint32_t* AL = reinterpret_cast<uint32_t*>(smc + F_AL);

    int tid = threadIdx.x;
    int wid = tid >> 5;
    int lane = tid & 31;
    int lg = lane >> 2;
    int lt = lane & 3;

    pack_w(Wa, WPa, tid);
    pack_w(Wb, WPb, tid);
    if (tid < 128) { bs1[tid] = ba[tid]; bs2[tid] = bb[tid]; }

    int ntiles = (M + 127) >> 7;
    for (int tile = blockIdx.x; tile < ntiles; tile += gridDim.x) {
        int row0 = tile << 7;
        __syncthreads();

        // ---- Load A tile, split hi/lo, store in mma A-frag order ----
#pragma unroll
        for (int j = 0; j < 16; j++) {
            int i4 = tid + 256 * j;
            int r = i4 >> 5;
            int q = i4 & 31;
            int k0 = q * 4;
            int gr = row0 + r;
            float4 v = make_float4(0.f, 0.f, 0.f, 0.f);
            if (gr < M)
                v = reinterpret_cast<const float4*>(A + (size_t)gr * D)[q];
            uint32_t h0 = bf2(v.y, v.x);
            uint32_t h1 = bf2(v.w, v.z);
            uint32_t l0 = bf2(v.y - bfhi(h0), v.x - bflo(h0));
            uint32_t l1 = bf2(v.w - bfhi(h1), v.z - bflo(h1));
            int mt = r >> 4;
            int g = r & 15;
            int ks = k0 >> 4;
            int kk = k0 & 15;
            int t0 = (kk & 7) >> 1;
            int reg = ((kk >= 8) ? 2 : 0) + ((g >= 8) ? 1 : 0);
            int base16 = (mt * 8 + ks) * 33 + (g & 7) * 4 + t0;
            AH[base16 * 4 + reg]       = h0;
            AH[(base16 + 1) * 4 + reg] = h1;
            AL[base16 * 4 + reg]       = l0;
            AL[(base16 + 1) * 4 + reg] = l1;
        }
        __syncthreads();

        // ---- Pass 1 ----
        float acc[16][4];
#pragma unroll
        for (int nt = 0; nt < 16; nt++)
#pragma unroll
            for (int j = 0; j < 4; j++) acc[nt][j] = 0.f;

#pragma unroll
        for (int ks = 0; ks < 8; ks++) {
            int ab = ((wid * 8 + ks) * 33 + lane) * 4;
            uint4 ah = *reinterpret_cast<uint4*>(&AH[ab]);
            uint4 al = *reinterpret_cast<uint4*>(&AL[ab]);
#pragma unroll
            for (int nt = 0; nt < 16; nt++) {
                uint4 w = WPa[(ks * 16 + nt) * 32 + lane];
                MMA(acc[nt][0], acc[nt][1], acc[nt][2], acc[nt][3],
                    ah.x, ah.y, ah.z, ah.w, w.x, w.y);
                MMA(acc[nt][0], acc[nt][1], acc[nt][2], acc[nt][3],
                    al.x, al.y, al.z, al.w, w.x, w.y);
                MMA(acc[nt][0], acc[nt][1], acc[nt][2], acc[nt][3],
                    ah.x, ah.y, ah.z, ah.w, w.z, w.w);
            }
        }

        // ---- Register epilogue 1 + A-frag build for pass 2 ----
        uint4 fah[8], fal[8];
#pragma unroll
        for (int ks = 0; ks < 8; ks++) {
            int nt0 = 2 * ks, nt1 = 2 * ks + 1;
            int c0 = nt0 * 8 + lt * 2;
            int c1 = nt1 * 8 + lt * 2;
            float t00 = fmaxf(acc[nt0][0] + bs1[c0],     0.f);
            float t01 = fmaxf(acc[nt0][1] + bs1[c0 + 1], 0.f);
            float t10 = fmaxf(acc[nt0][2] + bs1[c0],     0.f);
            float t11 = fmaxf(acc[nt0][3] + bs1[c0 + 1], 0.f);
            float u00 = fmaxf(acc[nt1][0] + bs1[c1],     0.f);
            float u01 = fmaxf(acc[nt1][1] + bs1[c1 + 1], 0.f);
            float u10 = fmaxf(acc[nt1][2] + bs1[c1],     0.f);
            float u11 = fmaxf(acc[nt1][3] + bs1[c1 + 1], 0.f);
            uint32_t h;
            h = bf2(t01, t00); fah[ks].x = h;
            fal[ks].x = bf2(t01 - bfhi(h), t00 - bflo(h));
            h = bf2(t11, t10); fah[ks].y = h;
            fal[ks].y = bf2(t11 - bfhi(h), t10 - bflo(h));
            h = bf2(u01, u00); fah[ks].z = h;
            fal[ks].z = bf2(u01 - bfhi(h), u00 - bflo(h));
            h = bf2(u11, u10); fah[ks].w = h;
            fal[ks].w = bf2(u11 - bfhi(h), u10 - bflo(h));
        }

        // ---- Pass 2 ----
#pragma unroll
        for (int nt = 0; nt < 16; nt++)
#pragma unroll
            for (int j = 0; j < 4; j++) acc[nt][j] = 0.f;

#pragma unroll
        for (int ks = 0; ks < 8; ks++) {
            uint4 ah = fah[ks];
            uint4 al = fal[ks];
#pragma unroll
            for (int nt = 0; nt < 16; nt++) {
                uint4 w = WPb[(ks * 16 + nt) * 32 + lane];
                MMA(acc[nt][0], acc[nt][1], acc[nt][2], acc[nt][3],
                    ah.x, ah.y, ah.z, ah.w, w.x, w.y);
                MMA(acc[nt][0], acc[nt][1], acc[nt][2], acc[nt][3],
                    al.x, al.y, al.z, al.w, w.x, w.y);
                MMA(acc[nt][0], acc[nt][1], acc[nt][2], acc[nt][3],
                    ah.x, ah.y, ah.z, ah.w, w.z, w.w);
            }
        }

        // ---- Epilogue 2: bias + relu + store ----
        int r0 = row0 + wid * 16 + lg;
        int r1 = r0 + 8;
#pragma unroll
        for (int nt = 0; nt < 16; nt++) {
            int c = nt * 8 + lt * 2;
            float b0v = bs2[c], b1v = bs2[c + 1];
            if (r0 < M) {
                float2 o;
                o.x = fmaxf(acc[nt][0] + b0v, 0.f);
                o.y = fmaxf(acc[nt][1] + b1v, 0.f);
                *reinterpret_cast<float2*>(out + (size_t)r0 * D + c) = o;
            }
            if (r1 < M) {
                float2 o;
                o.x = fmaxf(acc[nt][2] + b0v, 0.f);
                o.y = fmaxf(acc[nt][3] + b1v, 0.f);
                *reinterpret_cast<float2*>(out + (size_t)r1 * D + c) = o;
            }
        }
    }
}

// ===========================================================================
// Single GEMM (for FC head): out = relu(A@W + bias)
#define SM_BIAS 0
#define SM_W    512
#define SM_AH   66048
#define SM_AL   99840
#define TG_SMEM 133632

__global__ __launch_bounds__(256, 1)
void tgemm_kernel(const float* __restrict__ A, const float* __restrict__ W,
                  const float* __restrict__ bias, float* __restrict__ out,
                  int M) {
    extern __shared__ char smc[];
    float* bsm = reinterpret_cast<float*>(smc + SM_BIAS);
    uint4* WP  = reinterpret_cast<uint4*>(smc + SM_W);
    uint32_t* AH = reinterpret_cast<uint32_t*>(smc + SM_AH);
    uint32_t* AL = reinterpret_cast<uint32_t*>(smc + SM_AL);

    int tid = threadIdx.x;
    int wid = tid >> 5;
    int lane = tid & 31;
    int lg = lane >> 2;
    int lt = lane & 3;

    pack_w(W, WP, tid);
    if (tid < 128) bsm[tid] = bias[tid];

    int ntiles = (M + 127) >> 7;
    for (int tile = blockIdx.x; tile < ntiles; tile += gridDim.x) {
        int row0 = tile << 7;
        __syncthreads();
#pragma unroll
        for (int j = 0; j < 16; j++) {
            int i4 = tid + 256 * j;
            int r = i4 >> 5;
            int q = i4 & 31;
            int k0 = q * 4;
            int gr = row0 + r;
            float4 v = make_float4(0.f, 0.f, 0.f, 0.f);
            if (gr < M)
                v = reinterpret_cast<const float4*>(A + (size_t)gr * D)[q];
            uint32_t h0 = bf2(v.y, v.x);
            uint32_t h1 = bf2(v.w, v.z);
            uint32_t l0 = bf2(v.y - bfhi(h0), v.x - bflo(h0));
            uint32_t l1 = bf2(v.w - bfhi(h1), v.z - bflo(h1));
            int mt = r >> 4;
            int g = r & 15;
            int ks = k0 >> 4;
            int kk = k0 & 15;
            int t0 = (kk & 7) >> 1;
            int reg = ((kk >= 8) ? 2 : 0) + ((g >= 8) ? 1 : 0);
            int base16 = (mt * 8 + ks) * 33 + (g & 7) * 4 + t0;
            AH[base16 * 4 + reg]       = h0;
            AH[(base16 + 1) * 4 + reg] = h1;
            AL[base16 * 4 + reg]       = l0;
            AL[(base16 + 1) * 4 + reg] = l1;
        }
        __syncthreads();

        float acc[16][4];
#pragma unroll
        for (int nt = 0; nt < 16; nt++)
#pragma unroll
            for (int j = 0; j < 4; j++) acc[nt][j] = 0.f;

#pragma unroll
        for (int ks = 0; ks < 8; ks++) {
            int ab = ((wid * 8 + ks) * 33 + lane) * 4;
            uint4 ah = *reinterpret_cast<uint4*>(&AH[ab]);
            uint4 al = *reinterpret_cast<uint4*>(&AL[ab]);
#pragma unroll
            for (int nt = 0; nt < 16; nt++) {
                uint4 w = WP[(ks * 16 + nt) * 32 + lane];
                MMA(acc[nt][0], acc[nt][1], acc[nt][2], acc[nt][3],
                    ah.x, ah.y, ah.z, ah.w, w.x, w.y);
                MMA(acc[nt][0], acc[nt][1], acc[nt][2], acc[nt][3],
                    al.x, al.y, al.z, al.w, w.x, w.y);
                MMA(acc[nt][0], acc[nt][1], acc[nt][2], acc[nt][3],
                    ah.x, ah.y, ah.z, ah.w, w.z, w.w);
            }
        }

        int r0 = row0 + wid * 16 + lg;
        int r1 = r0 + 8;
#pragma unroll
        for (int nt = 0; nt < 16; nt++) {
            int c = nt * 8 + lt * 2;
            float b0v = bsm[c], b1v = bsm[c + 1];
            if (r0 < M) {
                float2 o;
                o.x = fmaxf(acc[nt][0] + b0v, 0.f);
                o.y = fmaxf(acc[nt][1] + b1v, 0.f);
                *reinterpret_cast<float2*>(out + (size_t)r0 * D + c) = o;
            }
            if (r1 < M) {
                float2 o;
                o.x = fmaxf(acc[nt][2] + b0v, 0.f);
                o.y = fmaxf(acc[nt][3] + b1v, 0.f);
                *reinterpret_cast<float2*>(out + (size_t)r1 * D + c) = o;
            }
        }
    }
}

// ---------------------------------------------------------------------------
extern "C" void kernel_launch(void* const* d_in, const int* in_sizes, int n_in,
                              void* d_out, int out_size) {
    const float* x = (const float*)d_in[0];
    const int* ei = (const int*)d_in[1];       // int32 (JAX x64 disabled)
    const int* batch = (const int*)d_in[2];    // int32
    const float* W1a = (const float*)d_in[3];
    const float* b1a = (const float*)d_in[4];
    const float* W1b = (const float*)d_in[5];
    const float* b1b = (const float*)d_in[6];
    const float* W2a = (const float*)d_in[7];
    const float* b2a = (const float*)d_in[8];
    const float* W2b = (const float*)d_in[9];
    const float* b2b = (const float*)d_in[10];
    const float* Wfc = (const float*)d_in[11];
    const float* bfc = (const float*)d_in[12];
    float* out = (float*)d_out;

    const int* src = ei;
    const int* dst = ei + NE;

    float *agg, *h, *pool;
    int *cnt, *adj;
    cudaGetSymbolAddress((void**)&agg, g_agg);
    cudaGetSymbolAddress((void**)&h, g_h);
    cudaGetSymbolAddress((void**)&pool, g_pool);
    cudaGetSymbolAddress((void**)&cnt, g_cnt);
    cudaGetSymbolAddress((void**)&adj, g_adj);

    cudaFuncSetAttribute(mlp_kernel,
                         cudaFuncAttributeMaxDynamicSharedMemorySize, F_SMEM);
    cudaFuncSetAttribute(tgemm_kernel,
                         cudaFuncAttributeMaxDynamicSharedMemorySize, TG_SMEM);

    // Adjacency build (cnt zeroed by pool_kernel each call) + pool zeroing
    build_kernel<<<1024, 256>>>(src, dst, cnt, adj, pool);

    // Layer 1: agg then fused MLP
    agg_kernel<<<2048, 256>>>(x, cnt, adj, agg);
    mlp_kernel<<<148, 256, F_SMEM>>>(agg, W1a, b1a, W1b, b1b, h, NN);

    // Layer 2
    agg_kernel<<<2048, 256>>>(h, cnt, adj, agg);
    mlp_kernel<<<148, 256, F_SMEM>>>(agg, W2a, b2a, W2b, b2b, h, NN);

    // Global add pool (also re-zeroes cnt) + FC head
    pool_kernel<<<784, 256>>>(h, batch, pool, cnt);
    tgemm_kernel<<<4, 256, TG_SMEM>>>(pool, Wfc, bfc, out, NG);
}